// round 10
// baseline (speedup 1.0000x reference)
#include <cuda_runtime.h>

#define N_NODES   50000
#define N_EDGES   800000
#define D         96
#define OUT_COLS  384            // 4 * D (concat of x,h1,h2,h3)
#define M_TILE    96             // rows per MLP block
#define IN_LD     97             // padded smem row stride (bank-conflict break)

// S_l = out[:, l*96 : (l+1)*96], row stride OUT_COLS. CSR scratch in globals.
__device__ int g_cnt[N_NODES];        // histogram, then fill cursors
__device__ int g_rowptr[N_NODES + 1];
__device__ int g_csr[N_EDGES];        // src ids grouped by dst

// ---------------------------------------------------------------------------
__global__ void init_kernel(const float* __restrict__ x, float* __restrict__ out) {
    int gid = blockIdx.x * blockDim.x + threadIdx.x;   // N_NODES*24 float4
    if (gid >= N_NODES * (D / 4)) return;
    int node = gid / (D / 4);
    int c    = gid % (D / 4);
    reinterpret_cast<float4*>(out + (size_t)node * OUT_COLS)[c] =
        reinterpret_cast<const float4*>(x)[gid];
}

__global__ void zero_cnt_kernel() {
    int i = blockIdx.x * blockDim.x + threadIdx.x;
    if (i < N_NODES) g_cnt[i] = 0;
}

__global__ void count_kernel(const int* __restrict__ ei) {
    int e = blockIdx.x * blockDim.x + threadIdx.x;
    if (e < N_EDGES) atomicAdd(&g_cnt[ei[N_EDGES + e]], 1);
}

// single-block exclusive scan over 50000 counts -> rowptr; cnt := rowptr (cursor)
__global__ void scan_kernel() {
    __shared__ int part[1024];
    const int t = threadIdx.x;
    const int CH = (N_NODES + 1023) / 1024;   // 49
    int base = t * CH;
    int s = 0;
    for (int i = 0; i < CH; ++i) {
        int idx = base + i;
        if (idx < N_NODES) s += g_cnt[idx];
    }
    part[t] = s;
    __syncthreads();
    for (int off = 1; off < 1024; off <<= 1) {
        int v = 0;
        if (t >= off) v = part[t - off];
        __syncthreads();
        if (t >= off) part[t] += v;
        __syncthreads();
    }
    int run = (t > 0) ? part[t - 1] : 0;      // exclusive prefix of this chunk
    for (int i = 0; i < CH; ++i) {
        int idx = base + i;
        if (idx < N_NODES) {
            int c = g_cnt[idx];
            g_rowptr[idx] = run;
            g_cnt[idx]    = run;              // fill cursor
            run += c;
        }
    }
    if (t == 1023) g_rowptr[N_NODES] = N_EDGES;
}

__global__ void fill_kernel(const int* __restrict__ ei) {
    int e = blockIdx.x * blockDim.x + threadIdx.x;
    if (e >= N_EDGES) return;
    int src = ei[e];
    int dst = ei[N_EDGES + e];
    int pos = atomicAdd(&g_cnt[dst], 1);
    g_csr[pos] = src;
}

// ---------------------------------------------------------------------------
// aggr: next[n] = cur[n] + sum_{src in in(n)} cur[src]
// 384 threads = 4 nodes x 96 cols; gather loop unrolled x4 (4 loads in flight)
// ---------------------------------------------------------------------------
__global__ void aggr_kernel(const float* __restrict__ cur,
                            float* __restrict__ next) {
    const int n = blockIdx.x * 4 + threadIdx.x / 96;
    const int c = threadIdx.x % 96;
    float acc = cur[(size_t)n * OUT_COLS + c];      // (1+eps)*h with eps=0
    int j   = g_rowptr[n];
    int end = g_rowptr[n + 1];
    for (; j + 4 <= end; j += 4) {
        int s0 = g_csr[j], s1 = g_csr[j + 1], s2 = g_csr[j + 2], s3 = g_csr[j + 3];
        float v0 = __ldg(&cur[(size_t)s0 * OUT_COLS + c]);
        float v1 = __ldg(&cur[(size_t)s1 * OUT_COLS + c]);
        float v2 = __ldg(&cur[(size_t)s2 * OUT_COLS + c]);
        float v3 = __ldg(&cur[(size_t)s3 * OUT_COLS + c]);
        acc += (v0 + v1) + (v2 + v3);
    }
    for (; j < end; ++j)
        acc += __ldg(&cur[(size_t)g_csr[j] * OUT_COLS + c]);
    next[(size_t)n * OUT_COLS + c] = acc;
}

// ---------------------------------------------------------------------------
// mlp: slice := relu(slice @ w1 + b1) @ w2 + b2   (in place, per-block safe)
// Block = 96 rows, 256 threads (tx=16, ty=16); micro-tile 6 rows x 6 cols.
// Smem: w(96x96) + in(96x97) + tmp(96x97) = 111360 B dynamic.
// ---------------------------------------------------------------------------
__global__ void mlp_kernel(const float* __restrict__ w1, const float* __restrict__ b1,
                           const float* __restrict__ w2, const float* __restrict__ b2,
                           float* __restrict__ slice) {
    extern __shared__ float smem[];
    float* sW   = smem;                    // 96*96
    float* sIn  = sW  + D * D;             // 96*97
    float* sTmp = sIn + M_TILE * IN_LD;    // 96*97

    const int tid = threadIdx.x;
    const int tx  = tid & 15;              // 6 cols each
    const int ty  = tid >> 4;              // 6 rows each
    const int rowBase = blockIdx.x * M_TILE;

    for (int i = tid; i < D * D / 4; i += 256)
        reinterpret_cast<float4*>(sW)[i] = reinterpret_cast<const float4*>(w1)[i];
    for (int i = tid; i < M_TILE * (D / 4); i += 256) {
        int r  = i / (D / 4);
        int cc = i % (D / 4);
        int row = rowBase + r;
        float4 v = make_float4(0.f, 0.f, 0.f, 0.f);
        if (row < N_NODES)
            v = *reinterpret_cast<const float4*>(slice + (size_t)row * OUT_COLS + cc * 4);
        float* dp = sIn + r * IN_LD + cc * 4;
        dp[0] = v.x; dp[1] = v.y; dp[2] = v.z; dp[3] = v.w;
    }
    __syncthreads();

    float acc[6][6];
    // ---- phase 1: tmp = relu(in @ w1 + b1) ----
    #pragma unroll
    for (int r = 0; r < 6; ++r)
        #pragma unroll
        for (int j = 0; j < 6; ++j) acc[r][j] = 0.f;

    #pragma unroll 4
    for (int k = 0; k < D; ++k) {
        float a[6], b[6];
        #pragma unroll
        for (int r = 0; r < 6; ++r) a[r] = sIn[(ty * 6 + r) * IN_LD + k];
        #pragma unroll
        for (int j = 0; j < 6; ++j) b[j] = sW[k * D + tx * 6 + j];
        #pragma unroll
        for (int r = 0; r < 6; ++r)
            #pragma unroll
            for (int j = 0; j < 6; ++j) acc[r][j] = fmaf(a[r], b[j], acc[r][j]);
    }
    #pragma unroll
    for (int r = 0; r < 6; ++r)
        #pragma unroll
        for (int j = 0; j < 6; ++j) {
            float v = acc[r][j] + b1[tx * 6 + j];
            sTmp[(ty * 6 + r) * IN_LD + tx * 6 + j] = fmaxf(v, 0.f);
        }
    __syncthreads();

    for (int i = tid; i < D * D / 4; i += 256)
        reinterpret_cast<float4*>(sW)[i] = reinterpret_cast<const float4*>(w2)[i];
    __syncthreads();

    // ---- phase 2: out = tmp @ w2 + b2 ----
    #pragma unroll
    for (int r = 0; r < 6; ++r)
        #pragma unroll
        for (int j = 0; j < 6; ++j) acc[r][j] = 0.f;

    #pragma unroll 4
    for (int k = 0; k < D; ++k) {
        float a[6], b[6];
        #pragma unroll
        for (int r = 0; r < 6; ++r) a[r] = sTmp[(ty * 6 + r) * IN_LD + k];
        #pragma unroll
        for (int j = 0; j < 6; ++j) b[j] = sW[k * D + tx * 6 + j];
        #pragma unroll
        for (int r = 0; r < 6; ++r)
            #pragma unroll
            for (int j = 0; j < 6; ++j) acc[r][j] = fmaf(a[r], b[j], acc[r][j]);
    }

    #pragma unroll
    for (int r = 0; r < 6; ++r) {
        int row = rowBase + ty * 6 + r;
        if (row >= N_NODES) continue;
        #pragma unroll
        for (int j = 0; j < 6; ++j) {
            int col = tx * 6 + j;
            slice[(size_t)row * OUT_COLS + col] = acc[r][j] + b2[col];
        }
    }
}

// ---------------------------------------------------------------------------
extern "C" void kernel_launch(void* const* d_in, const int* in_sizes, int n_in,
                              void* d_out, int out_size) {
    const float* x  = (const float*)d_in[0];
    const int*   ei = (const int*)d_in[1];
    const float* W[12];
    for (int i = 0; i < 12; ++i) W[i] = (const float*)d_in[2 + i];
    float* out = (float*)d_out;

    const int SMEM_BYTES = (D * D + 2 * M_TILE * IN_LD) * (int)sizeof(float); // 111360
    cudaFuncSetAttribute(mlp_kernel, cudaFuncAttributeMaxDynamicSharedMemorySize, SMEM_BYTES);

    init_kernel<<<(N_NODES * (D / 4) + 255) / 256, 256>>>(x, out);

    // CSR build (once per call; deterministic work, order-insensitive result)
    zero_cnt_kernel<<<(N_NODES + 255) / 256, 256>>>();
    count_kernel<<<(N_EDGES + 255) / 256, 256>>>(ei);
    scan_kernel<<<1, 1024>>>();
    fill_kernel<<<(N_EDGES + 255) / 256, 256>>>(ei);

    for (int l = 0; l < 3; ++l) {
        float* cur = out + (size_t)l * D;        // S_l (finalized h_l)
        float* agg = out + (size_t)(l + 1) * D;  // S_{l+1}
        aggr_kernel<<<N_NODES / 4, 384>>>(cur, agg);
        mlp_kernel<<<(N_NODES + M_TILE - 1) / M_TILE, 256, SMEM_BYTES>>>(
            W[4 * l + 0], W[4 * l + 1], W[4 * l + 2], W[4 * l + 3], agg);
    }
}

// round 11
// speedup vs baseline: 1.0839x; 1.0839x over previous
#include <cuda_runtime.h>

#define N_NODES   50000
#define N_EDGES   800000
#define D         96
#define OUT_COLS  384            // 4 * D (concat of x,h1,h2,h3)
#define M_TILE    96             // rows per MLP block
#define IN_LD     100            // padded smem row stride, 16B-aligned rows

#define SCAN_BS   512
#define SCAN_NB   ((N_NODES + SCAN_BS - 1) / SCAN_BS)   // 98

// S_l = out[:, l*96 : (l+1)*96], row stride OUT_COLS. CSR scratch in globals.
__device__ int g_cnt[N_NODES];          // histogram, then fill cursors
__device__ int g_rowptr[N_NODES + 1];
__device__ int g_csr[N_EDGES];          // src ids grouped by dst
__device__ int g_blksum[SCAN_NB];
__device__ int g_blkoff[SCAN_NB];

// ---------------------------------------------------------------------------
__global__ void init_kernel(const float* __restrict__ x, float* __restrict__ out) {
    int gid = blockIdx.x * blockDim.x + threadIdx.x;   // N_NODES*24 float4
    if (gid >= N_NODES * (D / 4)) return;
    int node = gid / (D / 4);
    int c    = gid % (D / 4);
    reinterpret_cast<float4*>(out + (size_t)node * OUT_COLS)[c] =
        reinterpret_cast<const float4*>(x)[gid];
}

__global__ void zero_cnt_kernel() {
    int i = blockIdx.x * blockDim.x + threadIdx.x;
    if (i < N_NODES) g_cnt[i] = 0;
}

__global__ void count_kernel(const int* __restrict__ ei) {
    int e = blockIdx.x * blockDim.x + threadIdx.x;
    if (e < N_EDGES) atomicAdd(&g_cnt[ei[N_EDGES + e]], 1);
}

// stage A: per-block exclusive scan of g_cnt -> g_rowptr (local), totals -> g_blksum
__global__ void scan_a_kernel() {
    __shared__ int sh[SCAN_BS];
    int t = threadIdx.x;
    int i = blockIdx.x * SCAN_BS + t;
    int v = (i < N_NODES) ? g_cnt[i] : 0;
    sh[t] = v;
    __syncthreads();
    int excl = 0;
    // Hillis-Steele inclusive scan, then shift
    for (int off = 1; off < SCAN_BS; off <<= 1) {
        int u = (t >= off) ? sh[t - off] : 0;
        __syncthreads();
        sh[t] += u;
        __syncthreads();
    }
    excl = sh[t] - v;
    if (i < N_NODES) g_rowptr[i] = excl;
    if (t == SCAN_BS - 1) g_blksum[blockIdx.x] = sh[t];
}

// stage B: 1 block scans SCAN_NB block sums (exclusive) -> g_blkoff
__global__ void scan_b_kernel() {
    __shared__ int sh[128];
    int t = threadIdx.x;                 // 128 threads
    int v = (t < SCAN_NB) ? g_blksum[t] : 0;
    sh[t] = v;
    __syncthreads();
    for (int off = 1; off < 128; off <<= 1) {
        int u = (t >= off) ? sh[t - off] : 0;
        __syncthreads();
        sh[t] += u;
        __syncthreads();
    }
    if (t < SCAN_NB) g_blkoff[t] = sh[t] - v;
}

// stage C: add block offsets; init fill cursors; cap rowptr
__global__ void scan_c_kernel() {
    int i = blockIdx.x * blockDim.x + threadIdx.x;
    if (i < N_NODES) {
        int r = g_rowptr[i] + g_blkoff[i / SCAN_BS];
        g_rowptr[i] = r;
        g_cnt[i]    = r;                 // cursor for fill
    }
    if (i == 0) g_rowptr[N_NODES] = N_EDGES;
}

__global__ void fill_kernel(const int* __restrict__ ei) {
    int e = blockIdx.x * blockDim.x + threadIdx.x;
    if (e >= N_EDGES) return;
    int src = ei[e];
    int dst = ei[N_EDGES + e];
    int pos = atomicAdd(&g_cnt[dst], 1);
    g_csr[pos] = src;
}

// ---------------------------------------------------------------------------
// aggr: next[n] = cur[n] + sum_{src in in(n)} cur[src]
// 384 threads = 4 nodes x 96 cols; gather loop unrolled x4
// ---------------------------------------------------------------------------
__global__ void aggr_kernel(const float* __restrict__ cur,
                            float* __restrict__ next) {
    const int n = blockIdx.x * 4 + threadIdx.x / 96;
    const int c = threadIdx.x % 96;
    float acc = cur[(size_t)n * OUT_COLS + c];      // (1+eps)*h with eps=0
    int j   = g_rowptr[n];
    int end = g_rowptr[n + 1];
    for (; j + 4 <= end; j += 4) {
        int s0 = g_csr[j], s1 = g_csr[j + 1], s2 = g_csr[j + 2], s3 = g_csr[j + 3];
        float v0 = __ldg(&cur[(size_t)s0 * OUT_COLS + c]);
        float v1 = __ldg(&cur[(size_t)s1 * OUT_COLS + c]);
        float v2 = __ldg(&cur[(size_t)s2 * OUT_COLS + c]);
        float v3 = __ldg(&cur[(size_t)s3 * OUT_COLS + c]);
        acc += (v0 + v1) + (v2 + v3);
    }
    for (; j < end; ++j)
        acc += __ldg(&cur[(size_t)g_csr[j] * OUT_COLS + c]);
    next[(size_t)n * OUT_COLS + c] = acc;
}

// ---------------------------------------------------------------------------
// mlp: slice := relu(slice @ w1 + b1) @ w2 + b2   (in place, per-block safe)
// Block = 96 rows, 256 threads (tx=16, ty=16); micro-tile 6 rows x 6 cols.
// k unrolled x4: a via LDS.128, b via LDS.64 (tx*6 even -> 8B aligned).
// Smem: w(96x96) + in(96x100) + tmp(96x100) = 113664 B dynamic.
// ---------------------------------------------------------------------------
__global__ void mlp_kernel(const float* __restrict__ w1, const float* __restrict__ b1,
                           const float* __restrict__ w2, const float* __restrict__ b2,
                           float* __restrict__ slice) {
    extern __shared__ float smem[];
    float* sW   = smem;                    // 96*96
    float* sIn  = sW  + D * D;             // 96*100
    float* sTmp = sIn + M_TILE * IN_LD;    // 96*100

    const int tid = threadIdx.x;
    const int tx  = tid & 15;              // 6 cols each
    const int ty  = tid >> 4;              // 6 rows each
    const int rowBase = blockIdx.x * M_TILE;

    for (int i = tid; i < D * D / 4; i += 256)
        reinterpret_cast<float4*>(sW)[i] = reinterpret_cast<const float4*>(w1)[i];
    for (int i = tid; i < M_TILE * (D / 4); i += 256) {
        int r  = i / (D / 4);
        int cc = i % (D / 4);
        int row = rowBase + r;
        float4 v = make_float4(0.f, 0.f, 0.f, 0.f);
        if (row < N_NODES)
            v = *reinterpret_cast<const float4*>(slice + (size_t)row * OUT_COLS + cc * 4);
        *reinterpret_cast<float4*>(sIn + r * IN_LD + cc * 4) = v;   // IN_LD%4==0
    }
    __syncthreads();

    float acc[6][6];
    // ---- phase 1: tmp = relu(in @ w1 + b1) ----
    #pragma unroll
    for (int r = 0; r < 6; ++r)
        #pragma unroll
        for (int j = 0; j < 6; ++j) acc[r][j] = 0.f;

    #pragma unroll
    for (int k = 0; k < D; k += 4) {
        float4 a4[6];
        #pragma unroll
        for (int r = 0; r < 6; ++r)
            a4[r] = *reinterpret_cast<const float4*>(sIn + (ty * 6 + r) * IN_LD + k);
        #pragma unroll
        for (int kk = 0; kk < 4; ++kk) {
            const float* bp = sW + (k + kk) * D + tx * 6;
            float2 b0 = *reinterpret_cast<const float2*>(bp);
            float2 b1v = *reinterpret_cast<const float2*>(bp + 2);
            float2 b2v = *reinterpret_cast<const float2*>(bp + 4);
            float b[6] = {b0.x, b0.y, b1v.x, b1v.y, b2v.x, b2v.y};
            #pragma unroll
            for (int r = 0; r < 6; ++r) {
                float a = kk == 0 ? a4[r].x : kk == 1 ? a4[r].y : kk == 2 ? a4[r].z : a4[r].w;
                #pragma unroll
                for (int j = 0; j < 6; ++j) acc[r][j] = fmaf(a, b[j], acc[r][j]);
            }
        }
    }
    #pragma unroll
    for (int r = 0; r < 6; ++r)
        #pragma unroll
        for (int j = 0; j < 6; ++j) {
            float v = acc[r][j] + b1[tx * 6 + j];
            sTmp[(ty * 6 + r) * IN_LD + tx * 6 + j] = fmaxf(v, 0.f);
        }
    __syncthreads();

    for (int i = tid; i < D * D / 4; i += 256)
        reinterpret_cast<float4*>(sW)[i] = reinterpret_cast<const float4*>(w2)[i];
    __syncthreads();

    // ---- phase 2: out = tmp @ w2 + b2 ----
    #pragma unroll
    for (int r = 0; r < 6; ++r)
        #pragma unroll
        for (int j = 0; j < 6; ++j) acc[r][j] = 0.f;

    #pragma unroll
    for (int k = 0; k < D; k += 4) {
        float4 a4[6];
        #pragma unroll
        for (int r = 0; r < 6; ++r)
            a4[r] = *reinterpret_cast<const float4*>(sTmp + (ty * 6 + r) * IN_LD + k);
        #pragma unroll
        for (int kk = 0; kk < 4; ++kk) {
            const float* bp = sW + (k + kk) * D + tx * 6;
            float2 b0 = *reinterpret_cast<const float2*>(bp);
            float2 b1v = *reinterpret_cast<const float2*>(bp + 2);
            float2 b2v = *reinterpret_cast<const float2*>(bp + 4);
            float b[6] = {b0.x, b0.y, b1v.x, b1v.y, b2v.x, b2v.y};
            #pragma unroll
            for (int r = 0; r < 6; ++r) {
                float a = kk == 0 ? a4[r].x : kk == 1 ? a4[r].y : kk == 2 ? a4[r].z : a4[r].w;
                #pragma unroll
                for (int j = 0; j < 6; ++j) acc[r][j] = fmaf(a, b[j], acc[r][j]);
            }
        }
    }

    #pragma unroll
    for (int r = 0; r < 6; ++r) {
        int row = rowBase + ty * 6 + r;
        if (row >= N_NODES) continue;
        #pragma unroll
        for (int j = 0; j < 6; ++j) {
            int col = tx * 6 + j;
            slice[(size_t)row * OUT_COLS + col] = acc[r][j] + b2[col];
        }
    }
}

// ---------------------------------------------------------------------------
extern "C" void kernel_launch(void* const* d_in, const int* in_sizes, int n_in,
                              void* d_out, int out_size) {
    const float* x  = (const float*)d_in[0];
    const int*   ei = (const int*)d_in[1];
    const float* W[12];
    for (int i = 0; i < 12; ++i) W[i] = (const float*)d_in[2 + i];
    float* out = (float*)d_out;

    const int SMEM_BYTES = (D * D + 2 * M_TILE * IN_LD) * (int)sizeof(float); // 113664
    cudaFuncSetAttribute(mlp_kernel, cudaFuncAttributeMaxDynamicSharedMemorySize, SMEM_BYTES);

    init_kernel<<<(N_NODES * (D / 4) + 255) / 256, 256>>>(x, out);

    // CSR build (hierarchical scan; all stages full-grid)
    zero_cnt_kernel<<<(N_NODES + 255) / 256, 256>>>();
    count_kernel<<<(N_EDGES + 255) / 256, 256>>>(ei);
    scan_a_kernel<<<SCAN_NB, SCAN_BS>>>();
    scan_b_kernel<<<1, 128>>>();
    scan_c_kernel<<<(N_NODES + 255) / 256, 256>>>();
    fill_kernel<<<(N_EDGES + 255) / 256, 256>>>(ei);

    for (int l = 0; l < 3; ++l) {
        float* cur = out + (size_t)l * D;        // S_l (finalized h_l)
        float* agg = out + (size_t)(l + 1) * D;  // S_{l+1}
        aggr_kernel<<<N_NODES / 4, 384>>>(cur, agg);
        mlp_kernel<<<(N_NODES + M_TILE - 1) / M_TILE, 256, SMEM_BYTES>>>(
            W[4 * l + 0], W[4 * l + 1], W[4 * l + 2], W[4 * l + 3], agg);
    }
}

// round 12
// speedup vs baseline: 1.2224x; 1.1278x over previous
#include <cuda_runtime.h>

#define N_NODES   50000
#define N_EDGES   800000
#define D         96
#define OUT_COLS  384            // 4 * D (concat of x,h1,h2,h3)
#define M_TILE    96             // rows per MLP block
#define IN_LD     100            // padded smem row stride, 16B-aligned rows

#define SCAN_BS   512
#define SCAN_NB   ((N_NODES + SCAN_BS - 1) / SCAN_BS)   // 98

// S_l = out[:, l*96 : (l+1)*96], row stride OUT_COLS. CSR scratch in globals.
__device__ int g_cnt[N_NODES];          // histogram, then fill cursors
__device__ int g_rowptr[N_NODES + 1];
__device__ int g_csr[N_EDGES];          // src ids grouped by dst
__device__ int g_blksum[SCAN_NB];
__device__ int g_blkoff[SCAN_NB];

// ---- packed fp32x2 helpers (FFMA2: 2 fp32 FMA per issue slot) -------------
typedef unsigned long long ull;
__device__ __forceinline__ ull pack2(float lo, float hi) {
    ull r; asm("mov.b64 %0, {%1, %2};" : "=l"(r) : "f"(lo), "f"(hi)); return r;
}
__device__ __forceinline__ void unpack2(ull v, float& lo, float& hi) {
    asm("mov.b64 {%0, %1}, %2;" : "=f"(lo), "=f"(hi) : "l"(v));
}
__device__ __forceinline__ void fma2(ull& d, ull a, ull b) {
    asm("fma.rn.f32x2 %0, %1, %2, %0;" : "+l"(d) : "l"(a), "l"(b));
}

// ---------------------------------------------------------------------------
__global__ void zero_cnt_kernel() {
    int i = blockIdx.x * blockDim.x + threadIdx.x;
    if (i < N_NODES) g_cnt[i] = 0;
}

__global__ void count_kernel(const int* __restrict__ ei) {
    int e = blockIdx.x * blockDim.x + threadIdx.x;
    if (e < N_EDGES) atomicAdd(&g_cnt[ei[N_EDGES + e]], 1);
}

// stage A: per-block exclusive scan of g_cnt -> g_rowptr, totals -> g_blksum
__global__ void scan_a_kernel() {
    __shared__ int sh[SCAN_BS];
    int t = threadIdx.x;
    int i = blockIdx.x * SCAN_BS + t;
    int v = (i < N_NODES) ? g_cnt[i] : 0;
    sh[t] = v;
    __syncthreads();
    for (int off = 1; off < SCAN_BS; off <<= 1) {
        int u = (t >= off) ? sh[t - off] : 0;
        __syncthreads();
        sh[t] += u;
        __syncthreads();
    }
    if (i < N_NODES) g_rowptr[i] = sh[t] - v;
    if (t == SCAN_BS - 1) g_blksum[blockIdx.x] = sh[t];
}

__global__ void scan_b_kernel() {
    __shared__ int sh[128];
    int t = threadIdx.x;
    int v = (t < SCAN_NB) ? g_blksum[t] : 0;
    sh[t] = v;
    __syncthreads();
    for (int off = 1; off < 128; off <<= 1) {
        int u = (t >= off) ? sh[t - off] : 0;
        __syncthreads();
        sh[t] += u;
        __syncthreads();
    }
    if (t < SCAN_NB) g_blkoff[t] = sh[t] - v;
}

__global__ void scan_c_kernel() {
    int i = blockIdx.x * blockDim.x + threadIdx.x;
    if (i < N_NODES) {
        int r = g_rowptr[i] + g_blkoff[i / SCAN_BS];
        g_rowptr[i] = r;
        g_cnt[i]    = r;                 // cursor for fill
    }
    if (i == 0) g_rowptr[N_NODES] = N_EDGES;
}

__global__ void fill_kernel(const int* __restrict__ ei) {
    int e = blockIdx.x * blockDim.x + threadIdx.x;
    if (e >= N_EDGES) return;
    int src = ei[e];
    int dst = ei[N_EDGES + e];
    int pos = atomicAdd(&g_cnt[dst], 1);
    g_csr[pos] = src;
}

// ---------------------------------------------------------------------------
// aggr: next[n] = cur[n] + sum_{src in in(n)} cur[src]; cur has row stride cs.
// selfcopy (optional) receives cur[n] (used for layer 0: S0 = x).
// 384 threads = 4 nodes x 96 cols; gather loop unrolled x4
// ---------------------------------------------------------------------------
__global__ void aggr_kernel(const float* __restrict__ cur, int cs,
                            float* __restrict__ selfcopy,
                            float* __restrict__ next) {
    const int n = blockIdx.x * 4 + threadIdx.x / 96;
    const int c = threadIdx.x % 96;
    float self = cur[(size_t)n * cs + c];
    float acc = self;                               // (1+eps)*h with eps=0
    int j   = g_rowptr[n];
    int end = g_rowptr[n + 1];
    for (; j + 4 <= end; j += 4) {
        int s0 = g_csr[j], s1 = g_csr[j + 1], s2 = g_csr[j + 2], s3 = g_csr[j + 3];
        float v0 = __ldg(&cur[(size_t)s0 * cs + c]);
        float v1 = __ldg(&cur[(size_t)s1 * cs + c]);
        float v2 = __ldg(&cur[(size_t)s2 * cs + c]);
        float v3 = __ldg(&cur[(size_t)s3 * cs + c]);
        acc += (v0 + v1) + (v2 + v3);
    }
    for (; j < end; ++j)
        acc += __ldg(&cur[(size_t)g_csr[j] * cs + c]);
    if (selfcopy) selfcopy[(size_t)n * OUT_COLS + c] = self;
    next[(size_t)n * OUT_COLS + c] = acc;
}

// ---------------------------------------------------------------------------
// mlp: slice := relu(slice @ w1 + b1) @ w2 + b2   (in place, per-block safe)
// Block = 96 rows, 256 threads (tx=16, ty=16); micro-tile 6 rows x 6 cols.
// Inner product uses packed fma.rn.f32x2 (FFMA2): col pairs packed in 64-bit.
// Smem: w(96x96) + in(96x100) + tmp(96x100) = 113664 B dynamic.
// ---------------------------------------------------------------------------
__global__ void mlp_kernel(const float* __restrict__ w1, const float* __restrict__ b1,
                           const float* __restrict__ w2, const float* __restrict__ b2,
                           float* __restrict__ slice) {
    extern __shared__ float smem[];
    float* sW   = smem;                    // 96*96
    float* sIn  = sW  + D * D;             // 96*100
    float* sTmp = sIn + M_TILE * IN_LD;    // 96*100

    const int tid = threadIdx.x;
    const int tx  = tid & 15;              // 6 cols each
    const int ty  = tid >> 4;              // 6 rows each
    const int rowBase = blockIdx.x * M_TILE;

    for (int i = tid; i < D * D / 4; i += 256)
        reinterpret_cast<float4*>(sW)[i] = reinterpret_cast<const float4*>(w1)[i];
    for (int i = tid; i < M_TILE * (D / 4); i += 256) {
        int r  = i / (D / 4);
        int cc = i % (D / 4);
        int row = rowBase + r;
        float4 v = make_float4(0.f, 0.f, 0.f, 0.f);
        if (row < N_NODES)
            v = *reinterpret_cast<const float4*>(slice + (size_t)row * OUT_COLS + cc * 4);
        *reinterpret_cast<float4*>(sIn + r * IN_LD + cc * 4) = v;
    }
    __syncthreads();

    ull acc2[6][3];
    const ull z = pack2(0.f, 0.f);

    // ---- phase 1: tmp = relu(in @ w1 + b1) ----
    #pragma unroll
    for (int r = 0; r < 6; ++r)
        #pragma unroll
        for (int jj = 0; jj < 3; ++jj) acc2[r][jj] = z;

    #pragma unroll 2
    for (int k = 0; k < D; k += 4) {
        float4 a4[6];
        #pragma unroll
        for (int r = 0; r < 6; ++r)
            a4[r] = *reinterpret_cast<const float4*>(sIn + (ty * 6 + r) * IN_LD + k);
        #pragma unroll
        for (int kk = 0; kk < 4; ++kk) {
            const float* bp = sW + (k + kk) * D + tx * 6;
            float2 q0 = *reinterpret_cast<const float2*>(bp);
            float2 q1 = *reinterpret_cast<const float2*>(bp + 2);
            float2 q2 = *reinterpret_cast<const float2*>(bp + 4);
            ull bb0 = pack2(q0.x, q0.y), bb1 = pack2(q1.x, q1.y), bb2 = pack2(q2.x, q2.y);
            #pragma unroll
            for (int r = 0; r < 6; ++r) {
                float a = kk == 0 ? a4[r].x : kk == 1 ? a4[r].y : kk == 2 ? a4[r].z : a4[r].w;
                ull a2 = pack2(a, a);
                fma2(acc2[r][0], a2, bb0);
                fma2(acc2[r][1], a2, bb1);
                fma2(acc2[r][2], a2, bb2);
            }
        }
    }
    #pragma unroll
    for (int r = 0; r < 6; ++r) {
        float* tp = sTmp + (ty * 6 + r) * IN_LD + tx * 6;
        #pragma unroll
        for (int jj = 0; jj < 3; ++jj) {
            float lo, hi; unpack2(acc2[r][jj], lo, hi);
            tp[jj * 2 + 0] = fmaxf(lo + b1[tx * 6 + jj * 2 + 0], 0.f);
            tp[jj * 2 + 1] = fmaxf(hi + b1[tx * 6 + jj * 2 + 1], 0.f);
        }
    }
    __syncthreads();

    for (int i = tid; i < D * D / 4; i += 256)
        reinterpret_cast<float4*>(sW)[i] = reinterpret_cast<const float4*>(w2)[i];
    __syncthreads();

    // ---- phase 2: out = tmp @ w2 + b2 ----
    #pragma unroll
    for (int r = 0; r < 6; ++r)
        #pragma unroll
        for (int jj = 0; jj < 3; ++jj) acc2[r][jj] = z;

    #pragma unroll 2
    for (int k = 0; k < D; k += 4) {
        float4 a4[6];
        #pragma unroll
        for (int r = 0; r < 6; ++r)
            a4[r] = *reinterpret_cast<const float4*>(sTmp + (ty * 6 + r) * IN_LD + k);
        #pragma unroll
        for (int kk = 0; kk < 4; ++kk) {
            const float* bp = sW + (k + kk) * D + tx * 6;
            float2 q0 = *reinterpret_cast<const float2*>(bp);
            float2 q1 = *reinterpret_cast<const float2*>(bp + 2);
            float2 q2 = *reinterpret_cast<const float2*>(bp + 4);
            ull bb0 = pack2(q0.x, q0.y), bb1 = pack2(q1.x, q1.y), bb2 = pack2(q2.x, q2.y);
            #pragma unroll
            for (int r = 0; r < 6; ++r) {
                float a = kk == 0 ? a4[r].x : kk == 1 ? a4[r].y : kk == 2 ? a4[r].z : a4[r].w;
                ull a2 = pack2(a, a);
                fma2(acc2[r][0], a2, bb0);
                fma2(acc2[r][1], a2, bb1);
                fma2(acc2[r][2], a2, bb2);
            }
        }
    }

    #pragma unroll
    for (int r = 0; r < 6; ++r) {
        int row = rowBase + ty * 6 + r;
        if (row >= N_NODES) continue;
        float* op = slice + (size_t)row * OUT_COLS + tx * 6;
        #pragma unroll
        for (int jj = 0; jj < 3; ++jj) {
            float lo, hi; unpack2(acc2[r][jj], lo, hi);
            op[jj * 2 + 0] = lo + b2[tx * 6 + jj * 2 + 0];
            op[jj * 2 + 1] = hi + b2[tx * 6 + jj * 2 + 1];
        }
    }
}

// ---------------------------------------------------------------------------
extern "C" void kernel_launch(void* const* d_in, const int* in_sizes, int n_in,
                              void* d_out, int out_size) {
    const float* x  = (const float*)d_in[0];
    const int*   ei = (const int*)d_in[1];
    const float* W[12];
    for (int i = 0; i < 12; ++i) W[i] = (const float*)d_in[2 + i];
    float* out = (float*)d_out;

    const int SMEM_BYTES = (D * D + 2 * M_TILE * IN_LD) * (int)sizeof(float); // 113664
    cudaFuncSetAttribute(mlp_kernel, cudaFuncAttributeMaxDynamicSharedMemorySize, SMEM_BYTES);

    // CSR build (hierarchical scan; all stages full-grid)
    zero_cnt_kernel<<<(N_NODES + 255) / 256, 256>>>();
    count_kernel<<<(N_EDGES + 255) / 256, 256>>>(ei);
    scan_a_kernel<<<SCAN_NB, SCAN_BS>>>();
    scan_b_kernel<<<1, 128>>>();
    scan_c_kernel<<<(N_NODES + 255) / 256, 256>>>();
    fill_kernel<<<(N_EDGES + 255) / 256, 256>>>(ei);

    for (int l = 0; l < 3; ++l) {
        const float* cur = (l == 0) ? x : out + (size_t)l * D;
        int cs           = (l == 0) ? D : OUT_COLS;
        float* selfcopy  = (l == 0) ? out : nullptr;   // S0 = x
        float* agg       = out + (size_t)(l + 1) * D;  // S_{l+1}
        aggr_kernel<<<N_NODES / 4, 384>>>(cur, cs, selfcopy, agg);
        mlp_kernel<<<(N_NODES + M_TILE - 1) / M_TILE, 256, SMEM_BYTES>>>(
            W[4 * l + 0], W[4 * l + 1], W[4 * l + 2], W[4 * l + 3], agg);
    }
}